// round 11
// baseline (speedup 1.0000x reference)
#include <cuda_runtime.h>

// Problem dims (fixed by the dataset; runtime values derived from in_sizes).
#define NMAX 50000
#define EMAX 800000

// ---- scratch (device globals; no allocation allowed) ----
__device__ float g_q[NMAX * 128];
__device__ float g_k[NMAX * 128];
__device__ float g_v[NMAX * 128];
__device__ float g_G[NMAX * 64];     // G[n,h*16+i] = sum_d We[i,h*32+d] * q[n,h*32+d]
__device__ float g_s[NMAX * 4];      // softmax denominators
__device__ float g_h1[NMAX * 32];    // layer-1 output (skip + attention)
__device__ float g_h2[NMAX * 32];    // layer-2 output
__device__ float g_us[NMAX * 32];    // relu(h2) @ Wm1[0:32]
__device__ float g_ud[NMAX * 32];    // relu(h2) @ Wm1[48:80]
__device__ float g_expa[EMAX * 4];   // exp(alpha) per SORTED edge position
__device__ float g_easorted[EMAX * 16];  // ea rows permuted into sorted order

// ---- CSR (dst-sorted edges), built once per launch ----
__device__ int g_deg[NMAX];
__device__ int g_rowptr[NMAX + 1];
__device__ int g_cursor[NMAX];
__device__ int g_srcsorted[EMAX];
__device__ int g_dstsorted[EMAX];
__device__ int g_eidsorted[EMAX];
__device__ int g_blocksums[256];     // (NMAX+255)/256 = 196 <= 256

// ===========================================================================
// CSR build: zero -> histogram -> 3-phase scan -> scatter -> ea permute
// ===========================================================================
__global__ void csr_zero_kernel(int N) {
    int i = blockIdx.x * blockDim.x + threadIdx.x;
    if (i < N) g_deg[i] = 0;
}

__global__ void csr_hist_kernel(const int* __restrict__ ei, int E) {
    int e = blockIdx.x * blockDim.x + threadIdx.x;
    if (e < E) atomicAdd(&g_deg[ei[E + e]], 1);
}

__global__ void csr_scan1_kernel(int N) {
    __shared__ int sh[256];
    int tid = threadIdx.x;
    int i = blockIdx.x * 256 + tid;
    int v = (i < N) ? g_deg[i] : 0;
    sh[tid] = v;
    __syncthreads();
#pragma unroll
    for (int off = 1; off < 256; off <<= 1) {
        int t = (tid >= off) ? sh[tid - off] : 0;
        __syncthreads();
        sh[tid] += t;
        __syncthreads();
    }
    if (i < N) g_rowptr[i + 1] = sh[tid];   // local inclusive, fixed in scan3
    if (tid == 255) g_blocksums[blockIdx.x] = sh[255];
}

__global__ void csr_scan2_kernel(int nb) {
    __shared__ int sh[256];
    int tid = threadIdx.x;
    int orig = (tid < nb) ? g_blocksums[tid] : 0;
    sh[tid] = orig;
    __syncthreads();
#pragma unroll
    for (int off = 1; off < 256; off <<= 1) {
        int t = (tid >= off) ? sh[tid - off] : 0;
        __syncthreads();
        sh[tid] += t;
        __syncthreads();
    }
    if (tid < nb) g_blocksums[tid] = sh[tid] - orig;  // exclusive
}

__global__ void csr_scan3_kernel(int N) {
    int i = blockIdx.x * blockDim.x + threadIdx.x;
    if (i < N) {
        int off = g_blocksums[i >> 8];
        int incl = g_rowptr[i + 1] + off;
        g_rowptr[i + 1] = incl;
        g_cursor[i] = incl - g_deg[i];
    }
    if (i == 0) g_rowptr[0] = 0;
}

__global__ void csr_scatter_kernel(const int* __restrict__ ei, int E) {
    int e = blockIdx.x * blockDim.x + threadIdx.x;
    if (e >= E) return;
    int src = ei[e];
    int dst = ei[E + e];
    int p = atomicAdd(&g_cursor[dst], 1);
    g_srcsorted[p] = src;
    g_dstsorted[p] = dst;
    g_eidsorted[p] = e;
}

// Permute ea rows into sorted order: 16 threads per row, coalesced writes.
__global__ void ea_sort_kernel(const float* __restrict__ ea, int E) {
    int idx = blockIdx.x * blockDim.x + threadIdx.x;
    int p = idx >> 4;
    int i = idx & 15;
    if (p < E)
        g_easorted[idx] = ea[(size_t)g_eidsorted[p] * 16 + i];
}

// ===========================================================================
// Zero softmax denominators.
// ===========================================================================
__global__ void zero_s_kernel(int n) {
    int i = blockIdx.x * blockDim.x + threadIdx.x;
    if (i < n) g_s[i] = 0.0f;
}

// ===========================================================================
// Node linears: q/k/v = x@W+b ([N,128]); skip = x@Ws+bs ([N,32]) into outbuf;
// G[n, w*16+i] = sum_d We[i, w*32+d] * q[n, w*32+d]  (warp w = head).
// One block per node, 128 threads.
// ===========================================================================
__global__ void node_linear_kernel(
    const float* __restrict__ xin, int layer,
    const float* __restrict__ Wq, const float* __restrict__ bq,
    const float* __restrict__ Wk, const float* __restrict__ bk,
    const float* __restrict__ Wv, const float* __restrict__ bv,
    const float* __restrict__ Ws, const float* __restrict__ bs,
    const float* __restrict__ We,
    int N)
{
    int n = blockIdx.x;
    if (n >= N) return;
    int j = threadIdx.x;  // 0..127
    int w = j >> 5;       // head
    int lane = j & 31;

    __shared__ float xs[32];
    if (j < 32) {
        float t = layer ? fmaxf(g_h1[n * 32 + j], 0.0f) : xin[n * 32 + j];
        xs[j] = t;
    }
    __syncthreads();

    float aq = bq[j], ak = bk[j], av = bv[j];
#pragma unroll
    for (int i = 0; i < 32; i++) {
        float xi = xs[i];
        aq = fmaf(xi, Wq[i * 128 + j], aq);
        ak = fmaf(xi, Wk[i * 128 + j], ak);
        av = fmaf(xi, Wv[i * 128 + j], av);
    }
    g_q[n * 128 + j] = aq;
    g_k[n * 128 + j] = ak;
    g_v[n * 128 + j] = av;

#pragma unroll
    for (int i = 0; i < 16; i++) {
        float t = We[i * 128 + j] * aq;
#pragma unroll
        for (int off = 16; off > 0; off >>= 1)
            t += __shfl_xor_sync(0xffffffffu, t, off);
        if (lane == 0) g_G[n * 64 + w * 16 + i] = t;
    }

    if (j < 32) {
        float as = bs[j];
#pragma unroll
        for (int i = 0; i < 32; i++) as = fmaf(xs[i], Ws[i * 32 + j], as);
        float* outbuf = layer ? g_h2 : g_h1;
        outbuf[n * 32 + j] = as;
    }
}

// ===========================================================================
// Pass A (sorted order): one warp per sorted edge position p. Fully parallel.
//   alpha_h = q[dst].k[src]|_h + sum_i ea_i * G[dst][h,i]
//   expa[p*4+h] = exp(alpha_h / sqrt(32));  s[dst,h] += expa_h (4-lane atomic)
// q/G loads L1-hit (consecutive warps share dst); ea is streaming.
// ===========================================================================
__global__ void edge_alpha_kernel(int E)
{
    int p = (int)((blockIdx.x * blockDim.x + threadIdx.x) >> 5);
    int lane = threadIdx.x & 31;
    if (p >= E) return;

    int src = g_srcsorted[p];
    int dst = g_dstsorted[p];

    float eav = (lane < 16) ? g_easorted[(size_t)p * 16 + lane] : 0.0f;

    const float* qrow = &g_q[dst * 128];
    const float* krow = &g_k[src * 128];
    float a0 = qrow[lane]      * krow[lane];
    float a1 = qrow[32 + lane] * krow[32 + lane];
    float a2 = qrow[64 + lane] * krow[64 + lane];
    float a3 = qrow[96 + lane] * krow[96 + lane];
    if (lane < 16) {
        const float* Grow = &g_G[dst * 64];
        a0 = fmaf(eav, Grow[lane],      a0);
        a1 = fmaf(eav, Grow[16 + lane], a1);
        a2 = fmaf(eav, Grow[32 + lane], a2);
        a3 = fmaf(eav, Grow[48 + lane], a3);
    }
#pragma unroll
    for (int off = 16; off >= 4; off >>= 1) {
        a0 += __shfl_xor_sync(0xffffffffu, a0, off);
        a1 += __shfl_xor_sync(0xffffffffu, a1, off);
        a2 += __shfl_xor_sync(0xffffffffu, a2, off);
        a3 += __shfl_xor_sync(0xffffffffu, a3, off);
    }
    int o = lane >> 3;
    float r = a0;
    if (o == 1) r = a1;
    else if (o == 2) r = a2;
    else if (o == 3) r = a3;
    r += __shfl_xor_sync(0xffffffffu, r, 1);
    r += __shfl_xor_sync(0xffffffffu, r, 2);

    float av = __expf(r * 0.17677669529663687f);  // 1/sqrt(32)
    if ((lane & 7) == 0) {
        g_expa[(size_t)p * 4 + o] = av;
        atomicAdd(&g_s[dst * 4 + o], av);  // 4 lanes/edge only
    }
}

// ===========================================================================
// Pass B: 4 sorted edges per warp. Gather-then-combine for max MLP.
//   a_h = expa_h / (s[dst,h]+1e-16)  (s known from pass A)
//   contrib[d] = sum_h a_h * v[src][h,d]   (heads collapsed in-register)
// Same-dst edges merged in registers; one 32-lane atomic per segment
// (~1.2 per 4 edges -> ~10 atomic lanes/edge). Flush is JUST an atomic.
// ===========================================================================
__global__ void edge_aggr4_kernel(int layer, int E, int nChunks)
{
    int c = (int)((blockIdx.x * blockDim.x + threadIdx.x) >> 5);
    int lane = threadIdx.x & 31;
    if (c >= nChunks) return;

    int p0 = c * 4;
    int nv = E - p0; if (nv > 4) nv = 4;

    int srcs[4], dsts[4];
    float4 evs[4];
#pragma unroll
    for (int u = 0; u < 4; u++) {
        if (u < nv) {
            srcs[u] = g_srcsorted[p0 + u];
            dsts[u] = g_dstsorted[p0 + u];
            evs[u] = *reinterpret_cast<const float4*>(&g_expa[(size_t)(p0 + u) * 4]);
        }
    }
    float vv[4][4], sv[4];
#pragma unroll
    for (int u = 0; u < 4; u++) {
        if (u < nv) {
            const float* vr = &g_v[(size_t)srcs[u] * 128];
            vv[u][0] = vr[lane];
            vv[u][1] = vr[32 + lane];
            vv[u][2] = vr[64 + lane];
            vv[u][3] = vr[96 + lane];
            sv[u] = g_s[dsts[u] * 4 + (lane & 3)];   // mostly L1-hit
        }
    }

    float* outbuf = layer ? g_h2 : g_h1;
    int cur = dsts[0];
    float acc = 0.0f;
#pragma unroll
    for (int u = 0; u < 4; u++) {
        if (u >= nv) break;
        if (dsts[u] != cur) {
            atomicAdd(&outbuf[cur * 32 + lane], 0.25f * acc);
            acc = 0.0f;
            cur = dsts[u];
        }
        float r = 1.0f / (sv[u] + 1e-16f);
        float i0 = __shfl_sync(0xffffffffu, r, 0);
        float i1 = __shfl_sync(0xffffffffu, r, 1);
        float i2 = __shfl_sync(0xffffffffu, r, 2);
        float i3 = __shfl_sync(0xffffffffu, r, 3);
        acc = fmaf(evs[u].x * i0, vv[u][0], acc);
        acc = fmaf(evs[u].y * i1, vv[u][1], acc);
        acc = fmaf(evs[u].z * i2, vv[u][2], acc);
        acc = fmaf(evs[u].w * i3, vv[u][3], acc);
    }
    atomicAdd(&outbuf[cur * 32 + lane], 0.25f * acc);
}

// ===========================================================================
// Finalize (e-part): warp per node, STREAMING loop (no gathers):
//   T[h,i] = sum_{p in seg(n)} expa[p,h] * easorted[p,i]   (registers)
//   out[n,d] += 0.25 * sum_h inv_h * sum_i We[i,h*32+d] * T[h,i]
// Runs after pass B -> plain read-modify-write, no atomics.
// ===========================================================================
__global__ void finalize_kernel(const float* __restrict__ We, int layer, int N)
{
    __shared__ float sWe[2048];  // 16 x 128
    for (int t = threadIdx.x; t < 2048; t += blockDim.x) sWe[t] = We[t];
    __syncthreads();

    int n = (int)((blockIdx.x * blockDim.x + threadIdx.x) >> 5);
    int lane = threadIdx.x & 31;
    if (n >= N) return;

    int rs = g_rowptr[n];
    int re = g_rowptr[n + 1];
    int hb = lane >> 4;

    float accT0 = 0.0f, accT1 = 0.0f;
#pragma unroll 4
    for (int p = rs; p < re; p++) {
        float4 ev = *reinterpret_cast<const float4*>(&g_expa[(size_t)p * 4]);  // broadcast
        float eav = g_easorted[(size_t)p * 16 + (lane & 15)];                  // 64B line
        accT0 = fmaf(hb ? ev.y : ev.x, eav, accT0);
        accT1 = fmaf(hb ? ev.w : ev.z, eav, accT1);
    }

    float sv = (lane < 4) ? 1.0f / (g_s[n * 4 + lane] + 1e-16f) : 0.0f;
    float i0 = __shfl_sync(0xffffffffu, sv, 0);
    float i1 = __shfl_sync(0xffffffffu, sv, 1);
    float i2 = __shfl_sync(0xffffffffu, sv, 2);
    float i3 = __shfl_sync(0xffffffffu, sv, 3);

    float ep = 0.0f;
#pragma unroll
    for (int h = 0; h < 4; h++) {
        float acc = 0.0f;
#pragma unroll
        for (int i = 0; i < 16; i++) {
            float t = (h < 2) ? __shfl_sync(0xffffffffu, accT0, h * 16 + i)
                              : __shfl_sync(0xffffffffu, accT1, (h - 2) * 16 + i);
            acc = fmaf(sWe[i * 128 + h * 32 + lane], t, acc);
        }
        float inv = (h == 0) ? i0 : (h == 1) ? i1 : (h == 2) ? i2 : i3;
        ep = fmaf(inv, acc, ep);
    }

    float* outbuf = layer ? g_h2 : g_h1;
    outbuf[n * 32 + lane] += 0.25f * ep;
}

// ===========================================================================
// MLP node precompute: u_src = relu(h2)@Wm1[0:32], u_dst = relu(h2)@Wm1[48:80]
// ===========================================================================
__global__ void mlp_pre_kernel(const float* __restrict__ Wm1, int N)
{
    __shared__ float sWa[1024];
    __shared__ float sWc[1024];
    for (int t = threadIdx.x; t < 1024; t += blockDim.x) {
        sWa[t] = Wm1[t];
        sWc[t] = Wm1[1536 + t];
    }
    __syncthreads();

    int n = (int)((blockIdx.x * blockDim.x + threadIdx.x) >> 5);
    int lane = threadIdx.x & 31;
    if (n >= N) return;

    float r = fmaxf(g_h2[n * 32 + lane], 0.0f);
    float us = 0.0f, ud = 0.0f;
#pragma unroll
    for (int i = 0; i < 32; i++) {
        float xi = __shfl_sync(0xffffffffu, r, i);
        us = fmaf(xi, sWa[i * 32 + lane], us);
        ud = fmaf(xi, sWc[i * 32 + lane], ud);
    }
    g_us[n * 32 + lane] = us;
    g_ud[n * 32 + lane] = ud;
}

// ===========================================================================
// Edge MLP: one warp per edge (original order; output is per original eid).
// ===========================================================================
__global__ void edge_mlp_kernel(
    const int* __restrict__ ei, const float* __restrict__ ea,
    const float* __restrict__ Wm1, const float* __restrict__ bm1,
    const float* __restrict__ Wm2, const float* __restrict__ bm2,
    float* __restrict__ out, int E)
{
    __shared__ float sWe2[512];
    __shared__ float sb1[32];
    __shared__ float sW2[32];
    for (int t = threadIdx.x; t < 512; t += blockDim.x) sWe2[t] = Wm1[1024 + t];
    if (threadIdx.x < 32) {
        sb1[threadIdx.x] = bm1[threadIdx.x];
        sW2[threadIdx.x] = Wm2[threadIdx.x];
    }
    __syncthreads();

    int e = (int)((blockIdx.x * blockDim.x + threadIdx.x) >> 5);
    int lane = threadIdx.x & 31;
    if (e >= E) return;

    int src = ei[e];
    int dst = ei[E + e];

    float eav = (lane < 16) ? ea[(size_t)e * 16 + lane] : 0.0f;

    float t = g_us[src * 32 + lane] + g_ud[dst * 32 + lane] + sb1[lane];
#pragma unroll
    for (int i = 0; i < 16; i++) {
        float xi = __shfl_sync(0xffffffffu, eav, i);
        t = fmaf(xi, sWe2[i * 32 + lane], t);
    }
    float o = fmaxf(t, 0.0f) * sW2[lane];
#pragma unroll
    for (int off = 16; off > 0; off >>= 1)
        o += __shfl_xor_sync(0xffffffffu, o, off);
    if (lane == 0) out[e] = o + bm2[0];
}

// ===========================================================================
extern "C" void kernel_launch(void* const* d_in, const int* in_sizes, int n_in,
                              void* d_out, int out_size)
{
    const float* x  = (const float*)d_in[0];
    const float* ea = (const float*)d_in[1];
    const int*   ei = (const int*)d_in[2];

    const float* Wq1 = (const float*)d_in[3];
    const float* bq1 = (const float*)d_in[4];
    const float* Wk1 = (const float*)d_in[5];
    const float* bk1 = (const float*)d_in[6];
    const float* Wv1 = (const float*)d_in[7];
    const float* bv1 = (const float*)d_in[8];
    const float* We1 = (const float*)d_in[9];
    const float* Ws1 = (const float*)d_in[10];
    const float* bs1 = (const float*)d_in[11];

    const float* Wq2 = (const float*)d_in[12];
    const float* bq2 = (const float*)d_in[13];
    const float* Wk2 = (const float*)d_in[14];
    const float* bk2 = (const float*)d_in[15];
    const float* Wv2 = (const float*)d_in[16];
    const float* bv2 = (const float*)d_in[17];
    const float* We2 = (const float*)d_in[18];
    const float* Ws2 = (const float*)d_in[19];
    const float* bs2 = (const float*)d_in[20];

    const float* Wm1 = (const float*)d_in[21];
    const float* bm1 = (const float*)d_in[22];
    const float* Wm2 = (const float*)d_in[23];
    const float* bm2 = (const float*)d_in[24];

    float* out = (float*)d_out;

    int N = in_sizes[0] / 32;
    int E = in_sizes[1] / 16;

    int nBlocks256     = (N + 255) / 256;
    int eBlocks256     = (E + 255) / 256;
    int edgeWarpBlocks = (E + 7) / 8;
    int nodeWarpBlocks = (N + 7) / 8;
    int nbScan         = (N + 255) / 256;
    int nChunks        = (E + 3) / 4;
    int chunkBlocks    = (nChunks + 7) / 8;
    int zeroBlocks     = (N * 4 + 255) / 256;
    int eaSortBlocks   = (E * 16 + 255) / 256;

    // ---- CSR build + sorted ea (shared by both layers) ----
    csr_zero_kernel<<<nBlocks256, 256>>>(N);
    csr_hist_kernel<<<eBlocks256, 256>>>(ei, E);
    csr_scan1_kernel<<<nbScan, 256>>>(N);
    csr_scan2_kernel<<<1, 256>>>(nbScan);
    csr_scan3_kernel<<<nBlocks256, 256>>>(N);
    csr_scatter_kernel<<<eBlocks256, 256>>>(ei, E);
    ea_sort_kernel<<<eaSortBlocks, 256>>>(ea, E);

    // ---- Layer 1 ----
    node_linear_kernel<<<N, 128>>>(x, 0, Wq1, bq1, Wk1, bk1, Wv1, bv1, Ws1, bs1, We1, N);
    zero_s_kernel<<<zeroBlocks, 256>>>(N * 4);
    edge_alpha_kernel<<<edgeWarpBlocks, 256>>>(E);
    edge_aggr4_kernel<<<chunkBlocks, 256>>>(0, E, nChunks);
    finalize_kernel<<<nodeWarpBlocks, 256>>>(We1, 0, N);

    // ---- Layer 2 ----
    node_linear_kernel<<<N, 128>>>(nullptr, 1, Wq2, bq2, Wk2, bk2, Wv2, bv2, Ws2, bs2, We2, N);
    zero_s_kernel<<<zeroBlocks, 256>>>(N * 4);
    edge_alpha_kernel<<<edgeWarpBlocks, 256>>>(E);
    edge_aggr4_kernel<<<chunkBlocks, 256>>>(1, E, nChunks);
    finalize_kernel<<<nodeWarpBlocks, 256>>>(We2, 1, N);

    // ---- Edge MLP ----
    mlp_pre_kernel<<<nodeWarpBlocks, 256>>>(Wm1, N);
    edge_mlp_kernel<<<edgeWarpBlocks, 256>>>(ei, ea, Wm1, bm1, Wm2, bm2, out, E);
}

// round 12
// speedup vs baseline: 1.1877x; 1.1877x over previous
#include <cuda_runtime.h>

// Problem dims (fixed by the dataset; runtime values derived from in_sizes).
#define NMAX 50000
#define EMAX 800000

// ---- scratch (device globals; no allocation allowed) ----
__device__ float g_q[NMAX * 128];
__device__ float g_k[NMAX * 128];
__device__ float g_v[NMAX * 128];
__device__ float g_G[NMAX * 64];    // G[n,h*16+i] = sum_d We[i,h*32+d] * q[n,h*32+d]
__device__ float g_h1[NMAX * 32];   // layer-1 output (skip + attention)
__device__ float g_h2[NMAX * 32];   // layer-2 output
__device__ float g_us[NMAX * 32];   // relu(h2) @ Wm1[0:32]
__device__ float g_ud[NMAX * 32];   // relu(h2) @ Wm1[48:80]

// ---- CSR (dst-sorted edges), built once per launch ----
__device__ int g_deg[NMAX];
__device__ int g_rowptr[NMAX + 1];
__device__ int g_cursor[NMAX];
__device__ int g_srcsorted[EMAX];
__device__ int g_eidsorted[EMAX];
__device__ int g_blocksums[256];    // (NMAX+255)/256 = 196 <= 256

// ===========================================================================
// CSR build: zero -> histogram -> 3-phase scan -> scatter
// ===========================================================================
__global__ void csr_zero_kernel(int N) {
    int i = blockIdx.x * blockDim.x + threadIdx.x;
    if (i < N) g_deg[i] = 0;
}

__global__ void csr_hist_kernel(const int* __restrict__ ei, int E) {
    int e = blockIdx.x * blockDim.x + threadIdx.x;
    if (e < E) atomicAdd(&g_deg[ei[E + e]], 1);
}

__global__ void csr_scan1_kernel(int N) {
    __shared__ int sh[256];
    int tid = threadIdx.x;
    int i = blockIdx.x * 256 + tid;
    int v = (i < N) ? g_deg[i] : 0;
    sh[tid] = v;
    __syncthreads();
#pragma unroll
    for (int off = 1; off < 256; off <<= 1) {
        int t = (tid >= off) ? sh[tid - off] : 0;
        __syncthreads();
        sh[tid] += t;
        __syncthreads();
    }
    if (i < N) g_rowptr[i + 1] = sh[tid];   // local inclusive, fixed in scan3
    if (tid == 255) g_blocksums[blockIdx.x] = sh[255];
}

__global__ void csr_scan2_kernel(int nb) {
    __shared__ int sh[256];
    int tid = threadIdx.x;
    int orig = (tid < nb) ? g_blocksums[tid] : 0;
    sh[tid] = orig;
    __syncthreads();
#pragma unroll
    for (int off = 1; off < 256; off <<= 1) {
        int t = (tid >= off) ? sh[tid - off] : 0;
        __syncthreads();
        sh[tid] += t;
        __syncthreads();
    }
    if (tid < nb) g_blocksums[tid] = sh[tid] - orig;  // exclusive
}

__global__ void csr_scan3_kernel(int N) {
    int i = blockIdx.x * blockDim.x + threadIdx.x;
    if (i < N) {
        int off = g_blocksums[i >> 8];
        int incl = g_rowptr[i + 1] + off;
        g_rowptr[i + 1] = incl;
        g_cursor[i] = incl - g_deg[i];
    }
    if (i == 0) g_rowptr[0] = 0;
}

__global__ void csr_scatter_kernel(const int* __restrict__ ei, int E) {
    int e = blockIdx.x * blockDim.x + threadIdx.x;
    if (e >= E) return;
    int src = ei[e];
    int dst = ei[E + e];
    int p = atomicAdd(&g_cursor[dst], 1);
    g_srcsorted[p] = src;
    g_eidsorted[p] = e;
}

// ===========================================================================
// Node linears: q/k/v = x@W+b ([N,128]); skip = x@Ws+bs ([N,32]) into outbuf;
// G[n, w*16+i] = sum_d We[i, w*32+d] * q[n, w*32+d]  (warp w = head).
// One block per node, 128 threads.
// ===========================================================================
__global__ void node_linear_kernel(
    const float* __restrict__ xin, int layer,
    const float* __restrict__ Wq, const float* __restrict__ bq,
    const float* __restrict__ Wk, const float* __restrict__ bk,
    const float* __restrict__ Wv, const float* __restrict__ bv,
    const float* __restrict__ Ws, const float* __restrict__ bs,
    const float* __restrict__ We,
    int N)
{
    int n = blockIdx.x;
    if (n >= N) return;
    int j = threadIdx.x;  // 0..127
    int w = j >> 5;       // head
    int lane = j & 31;

    __shared__ float xs[32];
    if (j < 32) {
        float t = layer ? fmaxf(g_h1[n * 32 + j], 0.0f) : xin[n * 32 + j];
        xs[j] = t;
    }
    __syncthreads();

    float aq = bq[j], ak = bk[j], av = bv[j];
#pragma unroll
    for (int i = 0; i < 32; i++) {
        float xi = xs[i];
        aq = fmaf(xi, Wq[i * 128 + j], aq);
        ak = fmaf(xi, Wk[i * 128 + j], ak);
        av = fmaf(xi, Wv[i * 128 + j], av);
    }
    g_q[n * 128 + j] = aq;
    g_k[n * 128 + j] = ak;
    g_v[n * 128 + j] = av;

#pragma unroll
    for (int i = 0; i < 16; i++) {
        float t = We[i * 128 + j] * aq;
#pragma unroll
        for (int off = 16; off > 0; off >>= 1)
            t += __shfl_xor_sync(0xffffffffu, t, off);
        if (lane == 0) g_G[n * 64 + w * 16 + i] = t;
    }

    if (j < 32) {
        float as = bs[j];
#pragma unroll
        for (int i = 0; i < 32; i++) as = fmaf(xs[i], Ws[i * 32 + j], as);
        float* outbuf = layer ? g_h2 : g_h1;
        outbuf[n * 32 + j] = as;
    }
}

// ===========================================================================
// Fused per-node attention, v2: TWO warps per node (stride-2 edge split),
// manual 2-edge interleaved chains, octet-trick reduce (19 shfl/edge),
// register accumulation, smem tail-merge. NO atomics, no extra passes.
// Block = 256 threads = 8 warps = 4 nodes.
// ===========================================================================
__global__ void __launch_bounds__(256, 3) node_attn_kernel(
    const float* __restrict__ ea,
    const float* __restrict__ We,
    int layer, int N)
{
    __shared__ float sWe[2048];        // 16 x 128
    __shared__ float smO[4][4][32];    // partner accO per node slot
    __shared__ float smT0[4][32];
    __shared__ float smT1[4][32];
    __shared__ float smS[4][4];

    for (int t = threadIdx.x; t < 2048; t += blockDim.x) sWe[t] = We[t];
    __syncthreads();

    int wid = threadIdx.x >> 5;     // 0..7
    int lane = threadIdx.x & 31;
    int local = wid >> 1;           // node slot 0..3
    int half = wid & 1;             // which warp of the pair
    int n = blockIdx.x * 4 + local;
    bool active = n < N;

    float q0 = 0, q1 = 0, q2 = 0, q3 = 0;
    float G0 = 0, G1 = 0, G2 = 0, G3 = 0;
    int rs = 0, re = 0;
    if (active) {
        rs = g_rowptr[n];
        re = g_rowptr[n + 1];
        const float* qrow = &g_q[n * 128];
        q0 = qrow[lane]; q1 = qrow[32 + lane]; q2 = qrow[64 + lane]; q3 = qrow[96 + lane];
        if (lane < 16) {
            const float* Grow = &g_G[n * 64];
            G0 = Grow[lane]; G1 = Grow[16 + lane]; G2 = Grow[32 + lane]; G3 = Grow[48 + lane];
        }
    }

    float accO0 = 0, accO1 = 0, accO2 = 0, accO3 = 0;
    float accT0 = 0, accT1 = 0;          // T[hb,i], T[2+hb,i]; hb=lane>>4, i=lane&15
    float s0 = 0, s1 = 0, s2 = 0, s3 = 0; // redundant across lanes
    int hb = lane >> 4;

    if (active) {
        for (int p = rs + half; p < re; p += 4) {
            int pa = p;
            int pb = p + 2;
            bool hasB = pb < re;
            int pbs = hasB ? pb : pa;   // safe dummy

            // ---- issue ALL loads for both edges up front ----
            int srcA = g_srcsorted[pa];
            int eidA = g_eidsorted[pa];
            int srcB = g_srcsorted[pbs];
            int eidB = g_eidsorted[pbs];

            float eavA = (lane < 16) ? ea[(size_t)eidA * 16 + lane] : 0.0f;
            float eavB = (lane < 16) ? ea[(size_t)eidB * 16 + lane] : 0.0f;

            const float* kA = &g_k[(size_t)srcA * 128];
            const float* kB = &g_k[(size_t)srcB * 128];
            const float* vA = &g_v[(size_t)srcA * 128];
            const float* vB = &g_v[(size_t)srcB * 128];

            float kA0 = kA[lane], kA1 = kA[32 + lane], kA2 = kA[64 + lane], kA3 = kA[96 + lane];
            float kB0 = kB[lane], kB1 = kB[32 + lane], kB2 = kB[64 + lane], kB3 = kB[96 + lane];
            float vA0 = vA[lane], vA1 = vA[32 + lane], vA2 = vA[64 + lane], vA3 = vA[96 + lane];
            float vB0 = vB[lane], vB1 = vB[32 + lane], vB2 = vB[64 + lane], vB3 = vB[96 + lane];

            // ---- two independent alpha chains, interleaved ----
            float a0 = fmaf(eavA, G0, q0 * kA0);
            float b0 = fmaf(eavB, G0, q0 * kB0);
            float a1 = fmaf(eavA, G1, q1 * kA1);
            float b1 = fmaf(eavB, G1, q1 * kB1);
            float a2 = fmaf(eavA, G2, q2 * kA2);
            float b2 = fmaf(eavB, G2, q2 * kB2);
            float a3 = fmaf(eavA, G3, q3 * kA3);
            float b3 = fmaf(eavB, G3, q3 * kB3);

#pragma unroll
            for (int off = 16; off >= 4; off >>= 1) {
                a0 += __shfl_xor_sync(0xffffffffu, a0, off);
                b0 += __shfl_xor_sync(0xffffffffu, b0, off);
                a1 += __shfl_xor_sync(0xffffffffu, a1, off);
                b1 += __shfl_xor_sync(0xffffffffu, b1, off);
                a2 += __shfl_xor_sync(0xffffffffu, a2, off);
                b2 += __shfl_xor_sync(0xffffffffu, b2, off);
                a3 += __shfl_xor_sync(0xffffffffu, a3, off);
                b3 += __shfl_xor_sync(0xffffffffu, b3, off);
            }
            // octet o takes head o; finish bits 0,1
            int o = lane >> 3;
            float rA = a0, rB = b0;
            if (o == 1) { rA = a1; rB = b1; }
            else if (o == 2) { rA = a2; rB = b2; }
            else if (o == 3) { rA = a3; rB = b3; }
            rA += __shfl_xor_sync(0xffffffffu, rA, 1);
            rB += __shfl_xor_sync(0xffffffffu, rB, 1);
            rA += __shfl_xor_sync(0xffffffffu, rA, 2);
            rB += __shfl_xor_sync(0xffffffffu, rB, 2);

            float avA = __expf(rA * 0.17677669529663687f);  // 1/sqrt(32)
            float avB = __expf(rB * 0.17677669529663687f);
            if (!hasB) avB = 0.0f;   // dummy edge contributes nothing (finite -> safe)

            float eA0 = __shfl_sync(0xffffffffu, avA, 0);
            float eB0 = __shfl_sync(0xffffffffu, avB, 0);
            float eA1 = __shfl_sync(0xffffffffu, avA, 8);
            float eB1 = __shfl_sync(0xffffffffu, avB, 8);
            float eA2 = __shfl_sync(0xffffffffu, avA, 16);
            float eB2 = __shfl_sync(0xffffffffu, avB, 16);
            float eA3 = __shfl_sync(0xffffffffu, avA, 24);
            float eB3 = __shfl_sync(0xffffffffu, avB, 24);

            // ---- accumulate ----
            accO0 = fmaf(eA0, vA0, accO0); accO0 = fmaf(eB0, vB0, accO0);
            accO1 = fmaf(eA1, vA1, accO1); accO1 = fmaf(eB1, vB1, accO1);
            accO2 = fmaf(eA2, vA2, accO2); accO2 = fmaf(eB2, vB2, accO2);
            accO3 = fmaf(eA3, vA3, accO3); accO3 = fmaf(eB3, vB3, accO3);

            float eaiA = __shfl_sync(0xffffffffu, eavA, lane & 15);
            float eaiB = __shfl_sync(0xffffffffu, eavB, lane & 15);
            accT0 = fmaf(hb ? eA1 : eA0, eaiA, accT0);
            accT0 = fmaf(hb ? eB1 : eB0, eaiB, accT0);
            accT1 = fmaf(hb ? eA3 : eA2, eaiA, accT1);
            accT1 = fmaf(hb ? eB3 : eB2, eaiB, accT1);

            s0 += eA0 + eB0;
            s1 += eA1 + eB1;
            s2 += eA2 + eB2;
            s3 += eA3 + eB3;
        }
    }

    // ---- merge partner halves via smem ----
    if (active && half == 1) {
        smO[local][0][lane] = accO0;
        smO[local][1][lane] = accO1;
        smO[local][2][lane] = accO2;
        smO[local][3][lane] = accO3;
        smT0[local][lane] = accT0;
        smT1[local][lane] = accT1;
        if (lane == 0) {
            smS[local][0] = s0; smS[local][1] = s1;
            smS[local][2] = s2; smS[local][3] = s3;
        }
    }
    __syncthreads();

    if (active && half == 0) {
        accO0 += smO[local][0][lane];
        accO1 += smO[local][1][lane];
        accO2 += smO[local][2][lane];
        accO3 += smO[local][3][lane];
        accT0 += smT0[local][lane];
        accT1 += smT1[local][lane];
        s0 += smS[local][0];
        s1 += smS[local][1];
        s2 += smS[local][2];
        s3 += smS[local][3];

        float inv0 = 1.0f / (s0 + 1e-16f);
        float inv1 = 1.0f / (s1 + 1e-16f);
        float inv2 = 1.0f / (s2 + 1e-16f);
        float inv3 = 1.0f / (s3 + 1e-16f);

        // v-part
        float res = inv0 * accO0;
        res = fmaf(inv1, accO1, res);
        res = fmaf(inv2, accO2, res);
        res = fmaf(inv3, accO3, res);

        // e-part: sum_h inv_h * sum_i We[i, h*32+lane] * T[h,i]
#pragma unroll
        for (int h = 0; h < 4; h++) {
            float acc = 0.0f;
#pragma unroll
            for (int i = 0; i < 16; i++) {
                float t = (h < 2) ? __shfl_sync(0xffffffffu, accT0, h * 16 + i)
                                  : __shfl_sync(0xffffffffu, accT1, (h - 2) * 16 + i);
                acc = fmaf(sWe[i * 128 + h * 32 + lane], t, acc);
            }
            float inv = (h == 0) ? inv0 : (h == 1) ? inv1 : (h == 2) ? inv2 : inv3;
            res = fmaf(inv, acc, res);
        }

        float* outbuf = layer ? g_h2 : g_h1;
        outbuf[n * 32 + lane] += 0.25f * res;   // skip already there; no atomics
    }
}

// ===========================================================================
// MLP node precompute: u_src = relu(h2)@Wm1[0:32], u_dst = relu(h2)@Wm1[48:80]
// ===========================================================================
__global__ void mlp_pre_kernel(const float* __restrict__ Wm1, int N)
{
    __shared__ float sWa[1024];
    __shared__ float sWc[1024];
    for (int t = threadIdx.x; t < 1024; t += blockDim.x) {
        sWa[t] = Wm1[t];
        sWc[t] = Wm1[1536 + t];
    }
    __syncthreads();

    int n = (int)((blockIdx.x * blockDim.x + threadIdx.x) >> 5);
    int lane = threadIdx.x & 31;
    if (n >= N) return;

    float r = fmaxf(g_h2[n * 32 + lane], 0.0f);
    float us = 0.0f, ud = 0.0f;
#pragma unroll
    for (int i = 0; i < 32; i++) {
        float xi = __shfl_sync(0xffffffffu, r, i);
        us = fmaf(xi, sWa[i * 32 + lane], us);
        ud = fmaf(xi, sWc[i * 32 + lane], ud);
    }
    g_us[n * 32 + lane] = us;
    g_ud[n * 32 + lane] = ud;
}

// ===========================================================================
// Edge MLP: one warp per edge.
// ===========================================================================
__global__ void edge_mlp_kernel(
    const int* __restrict__ ei, const float* __restrict__ ea,
    const float* __restrict__ Wm1, const float* __restrict__ bm1,
    const float* __restrict__ Wm2, const float* __restrict__ bm2,
    float* __restrict__ out, int E)
{
    __shared__ float sWe2[512];
    __shared__ float sb1[32];
    __shared__ float sW2[32];
    for (int t = threadIdx.x; t < 512; t += blockDim.x) sWe2[t] = Wm1[1024 + t];
    if (threadIdx.x < 32) {
        sb1[threadIdx.x] = bm1[threadIdx.x];
        sW2[threadIdx.x] = Wm2[threadIdx.x];
    }
    __syncthreads();

    int e = (int)((blockIdx.x * blockDim.x + threadIdx.x) >> 5);
    int lane = threadIdx.x & 31;
    if (e >= E) return;

    int src = ei[e];
    int dst = ei[E + e];

    float eav = (lane < 16) ? ea[(size_t)e * 16 + lane] : 0.0f;

    float t = g_us[src * 32 + lane] + g_ud[dst * 32 + lane] + sb1[lane];
#pragma unroll
    for (int i = 0; i < 16; i++) {
        float xi = __shfl_sync(0xffffffffu, eav, i);
        t = fmaf(xi, sWe2[i * 32 + lane], t);
    }
    float o = fmaxf(t, 0.0f) * sW2[lane];
#pragma unroll
    for (int off = 16; off > 0; off >>= 1)
        o += __shfl_xor_sync(0xffffffffu, o, off);
    if (lane == 0) out[e] = o + bm2[0];
}

// ===========================================================================
extern "C" void kernel_launch(void* const* d_in, const int* in_sizes, int n_in,
                              void* d_out, int out_size)
{
    const float* x  = (const float*)d_in[0];
    const float* ea = (const float*)d_in[1];
    const int*   ei = (const int*)d_in[2];

    const float* Wq1 = (const float*)d_in[3];
    const float* bq1 = (const float*)d_in[4];
    const float* Wk1 = (const float*)d_in[5];
    const float* bk1 = (const float*)d_in[6];
    const float* Wv1 = (const float*)d_in[7];
    const float* bv1 = (const float*)d_in[8];
    const float* We1 = (const float*)d_in[9];
    const float* Ws1 = (const float*)d_in[10];
    const float* bs1 = (const float*)d_in[11];

    const float* Wq2 = (const float*)d_in[12];
    const float* bq2 = (const float*)d_in[13];
    const float* Wk2 = (const float*)d_in[14];
    const float* bk2 = (const float*)d_in[15];
    const float* Wv2 = (const float*)d_in[16];
    const float* bv2 = (const float*)d_in[17];
    const float* We2 = (const float*)d_in[18];
    const float* Ws2 = (const float*)d_in[19];
    const float* bs2 = (const float*)d_in[20];

    const float* Wm1 = (const float*)d_in[21];
    const float* bm1 = (const float*)d_in[22];
    const float* Wm2 = (const float*)d_in[23];
    const float* bm2 = (const float*)d_in[24];

    float* out = (float*)d_out;

    int N = in_sizes[0] / 32;
    int E = in_sizes[1] / 16;

    int nBlocks256     = (N + 255) / 256;
    int eBlocks256     = (E + 255) / 256;
    int edgeWarpBlocks = (E + 7) / 8;
    int nodeWarpBlocks = (N + 7) / 8;
    int nbScan         = (N + 255) / 256;
    int attnBlocks     = (N + 3) / 4;   // 4 nodes per 256-thread block (2 warps/node)

    // ---- CSR build (shared by both layers) ----
    csr_zero_kernel<<<nBlocks256, 256>>>(N);
    csr_hist_kernel<<<eBlocks256, 256>>>(ei, E);
    csr_scan1_kernel<<<nbScan, 256>>>(N);
    csr_scan2_kernel<<<1, 256>>>(nbScan);
    csr_scan3_kernel<<<nBlocks256, 256>>>(N);
    csr_scatter_kernel<<<eBlocks256, 256>>>(ei, E);

    // ---- Layer 1 ----
    node_linear_kernel<<<N, 128>>>(x, 0, Wq1, bq1, Wk1, bk1, Wv1, bv1, Ws1, bs1, We1, N);
    node_attn_kernel<<<attnBlocks, 256>>>(ea, We1, 0, N);

    // ---- Layer 2 ----
    node_linear_kernel<<<N, 128>>>(nullptr, 1, Wq2, bq2, Wk2, bk2, Wv2, bv2, Ws2, bs2, We2, N);
    node_attn_kernel<<<attnBlocks, 256>>>(ea, We2, 1, N);

    // ---- Edge MLP ----
    mlp_pre_kernel<<<nodeWarpBlocks, 256>>>(Wm1, N);
    edge_mlp_kernel<<<edgeWarpBlocks, 256>>>(ei, ea, Wm1, bm1, Wm2, bm2, out, E);
}

// round 14
// speedup vs baseline: 1.2350x; 1.0398x over previous
#include <cuda_runtime.h>

// Problem dims (fixed by the dataset; runtime values derived from in_sizes).
#define NMAX 50000
#define EMAX 800000

// ---- scratch (device globals; no allocation allowed) ----
__device__ float g_q[NMAX * 128];
__device__ float g_kv[NMAX * 256];  // k row [0:128), v row [128:256) per node
__device__ float g_G[NMAX * 64];    // G[n,h*16+i] = sum_d We[i,h*32+d] * q[n,h*32+d]
__device__ float g_h1[NMAX * 32];   // layer-1 output (skip + attention)
__device__ float g_h2[NMAX * 32];   // layer-2 output
__device__ float g_us[NMAX * 32];   // relu(h2) @ Wm1[0:32]
__device__ float g_ud[NMAX * 32];   // relu(h2) @ Wm1[48:80]
__device__ float g_easorted[EMAX * 16];  // ea rows permuted into dst-sorted order

// ---- CSR (dst-sorted edges), built once per launch ----
__device__ int g_deg[NMAX];
__device__ int g_rowptr[NMAX + 1];
__device__ int g_cursor[NMAX];
__device__ int g_srcsorted[EMAX];
__device__ int g_eidsorted[EMAX];

// ===========================================================================
// CSR build: (deg zeroed inside node_linear) -> histogram -> single-block
// scan -> scatter -> ea permute
// ===========================================================================
__global__ void csr_hist_kernel(const int* __restrict__ ei, int E) {
    int e = blockIdx.x * blockDim.x + threadIdx.x;
    if (e < E) atomicAdd(&g_deg[ei[E + e]], 1);
}

// Single-block exclusive scan over g_deg -> g_rowptr / g_cursor.
__global__ void csr_scan_kernel(int N) {
    __shared__ int warpsums[32];
    __shared__ int s_carry;
    int tid = threadIdx.x;
    int lane = tid & 31;
    int w = tid >> 5;
    if (tid == 0) s_carry = 0;
    __syncthreads();

    for (int base = 0; base < N; base += 1024) {
        int i = base + tid;
        int v = (i < N) ? g_deg[i] : 0;
        // warp inclusive scan
        int x = v;
#pragma unroll
        for (int off = 1; off < 32; off <<= 1) {
            int t = __shfl_up_sync(0xffffffffu, x, off);
            if (lane >= off) x += t;
        }
        if (lane == 31) warpsums[w] = x;
        __syncthreads();
        if (w == 0) {
            int y = warpsums[lane];
#pragma unroll
            for (int off = 1; off < 32; off <<= 1) {
                int t = __shfl_up_sync(0xffffffffu, y, off);
                if (lane >= off) y += t;
            }
            warpsums[lane] = y;
        }
        __syncthreads();
        int incl = x + (w ? warpsums[w - 1] : 0) + s_carry;
        if (i < N) {
            g_rowptr[i + 1] = incl;
            g_cursor[i] = incl - v;
        }
        __syncthreads();               // everyone has read s_carry
        if (tid == 1023) s_carry = incl;
        __syncthreads();
    }
    if (tid == 0) g_rowptr[0] = 0;
}

__global__ void csr_scatter_kernel(const int* __restrict__ ei, int E) {
    int e = blockIdx.x * blockDim.x + threadIdx.x;
    if (e >= E) return;
    int src = ei[e];
    int dst = ei[E + e];
    int p = atomicAdd(&g_cursor[dst], 1);
    g_srcsorted[p] = src;
    g_eidsorted[p] = e;
}

// Permute ea rows into sorted order: 16 threads per row, coalesced writes.
__global__ void ea_sort_kernel(const float* __restrict__ ea, int E) {
    int idx = blockIdx.x * blockDim.x + threadIdx.x;
    int p = idx >> 4;
    int i = idx & 15;
    if (p < E)
        g_easorted[idx] = ea[(size_t)g_eidsorted[p] * 16 + i];
}

// ===========================================================================
// Node linears: q = x@Wq+b ([N,128]); k,v interleaved into g_kv;
// skip = x@Ws+bs ([N,32]) into outbuf;
// G[n, w*16+i] = sum_d We[i, w*32+d] * q[n, w*32+d]  (warp w = head).
// One block per node, 128 threads. Layer 0 also zeroes g_deg.
// ===========================================================================
__global__ void node_linear_kernel(
    const float* __restrict__ xin, int layer,
    const float* __restrict__ Wq, const float* __restrict__ bq,
    const float* __restrict__ Wk, const float* __restrict__ bk,
    const float* __restrict__ Wv, const float* __restrict__ bv,
    const float* __restrict__ Ws, const float* __restrict__ bs,
    const float* __restrict__ We,
    int N)
{
    int n = blockIdx.x;
    if (n >= N) return;
    int j = threadIdx.x;  // 0..127
    int w = j >> 5;       // head
    int lane = j & 31;

    if (layer == 0 && j == 0) g_deg[n] = 0;   // prep for CSR histogram

    __shared__ float xs[32];
    if (j < 32) {
        float t = layer ? fmaxf(g_h1[n * 32 + j], 0.0f) : xin[n * 32 + j];
        xs[j] = t;
    }
    __syncthreads();

    float aq = bq[j], ak = bk[j], av = bv[j];
#pragma unroll
    for (int i = 0; i < 32; i++) {
        float xi = xs[i];
        aq = fmaf(xi, Wq[i * 128 + j], aq);
        ak = fmaf(xi, Wk[i * 128 + j], ak);
        av = fmaf(xi, Wv[i * 128 + j], av);
    }
    g_q[n * 128 + j] = aq;
    g_kv[(size_t)n * 256 + j] = ak;
    g_kv[(size_t)n * 256 + 128 + j] = av;

#pragma unroll
    for (int i = 0; i < 16; i++) {
        float t = We[i * 128 + j] * aq;
#pragma unroll
        for (int off = 16; off > 0; off >>= 1)
            t += __shfl_xor_sync(0xffffffffu, t, off);
        if (lane == 0) g_G[n * 64 + w * 16 + i] = t;
    }

    if (j < 32) {
        float as = bs[j];
#pragma unroll
        for (int i = 0; i < 32; i++) as = fmaf(xs[i], Ws[i * 32 + j], as);
        float* outbuf = layer ? g_h2 : g_h1;
        outbuf[n * 32 + j] = as;
    }
}

// ===========================================================================
// Fused per-node attention: one warp per node, CSR loop, register
// accumulation, NO atomics. ea is STREAMING (easorted), kv is one 1KB record.
// ===========================================================================
__global__ void node_attn_kernel(const float* __restrict__ We,
                                 int layer, int N)
{
    __shared__ float sWe[2048];  // 16 x 128
    for (int t = threadIdx.x; t < 2048; t += blockDim.x) sWe[t] = We[t];
    __syncthreads();

    int n = (int)((blockIdx.x * blockDim.x + threadIdx.x) >> 5);
    int lane = threadIdx.x & 31;
    if (n >= N) return;

    int rs = g_rowptr[n];
    int re = g_rowptr[n + 1];

    const float* qrow = &g_q[n * 128];
    float q0 = qrow[lane], q1 = qrow[32 + lane], q2 = qrow[64 + lane], q3 = qrow[96 + lane];
    float G0 = 0, G1 = 0, G2 = 0, G3 = 0;
    if (lane < 16) {
        const float* Grow = &g_G[n * 64];
        G0 = Grow[lane]; G1 = Grow[16 + lane]; G2 = Grow[32 + lane]; G3 = Grow[48 + lane];
    }

    float accO0 = 0, accO1 = 0, accO2 = 0, accO3 = 0;
    float accT0 = 0, accT1 = 0;            // T[hb,i], T[2+hb,i]
    float s0 = 0, s1 = 0, s2 = 0, s3 = 0;  // redundant across lanes
    int hb = lane >> 4;

#pragma unroll 2
    for (int p = rs; p < re; p++) {
        int src = g_srcsorted[p];
        float eav = (lane < 16) ? g_easorted[(size_t)p * 16 + lane] : 0.0f;

        const float* kv = &g_kv[(size_t)src * 256];
        float k0 = kv[lane], k1 = kv[32 + lane], k2 = kv[64 + lane], k3 = kv[96 + lane];
        float v0 = kv[128 + lane], v1 = kv[160 + lane], v2 = kv[192 + lane], v3 = kv[224 + lane];

        float a0 = fmaf(eav, G0, q0 * k0);
        float a1 = fmaf(eav, G1, q1 * k1);
        float a2 = fmaf(eav, G2, q2 * k2);
        float a3 = fmaf(eav, G3, q3 * k3);
#pragma unroll
        for (int off = 16; off >= 4; off >>= 1) {
            a0 += __shfl_xor_sync(0xffffffffu, a0, off);
            a1 += __shfl_xor_sync(0xffffffffu, a1, off);
            a2 += __shfl_xor_sync(0xffffffffu, a2, off);
            a3 += __shfl_xor_sync(0xffffffffu, a3, off);
        }
        // octet o takes head o; finish bits 0,1
        int o = lane >> 3;
        float r = a0;
        if (o == 1) r = a1;
        else if (o == 2) r = a2;
        else if (o == 3) r = a3;
        r += __shfl_xor_sync(0xffffffffu, r, 1);
        r += __shfl_xor_sync(0xffffffffu, r, 2);

        float av = __expf(r * 0.17677669529663687f);  // 1/sqrt(32)
        float e0 = __shfl_sync(0xffffffffu, av, 0);
        float e1 = __shfl_sync(0xffffffffu, av, 8);
        float e2 = __shfl_sync(0xffffffffu, av, 16);
        float e3 = __shfl_sync(0xffffffffu, av, 24);

        accO0 = fmaf(e0, v0, accO0);
        accO1 = fmaf(e1, v1, accO1);
        accO2 = fmaf(e2, v2, accO2);
        accO3 = fmaf(e3, v3, accO3);

        float eai = __shfl_sync(0xffffffffu, eav, lane & 15);
        accT0 = fmaf(hb ? e1 : e0, eai, accT0);
        accT1 = fmaf(hb ? e3 : e2, eai, accT1);

        s0 += e0; s1 += e1; s2 += e2; s3 += e3;
    }

    float inv0 = 1.0f / (s0 + 1e-16f);
    float inv1 = 1.0f / (s1 + 1e-16f);
    float inv2 = 1.0f / (s2 + 1e-16f);
    float inv3 = 1.0f / (s3 + 1e-16f);

    // v-part
    float res = inv0 * accO0;
    res = fmaf(inv1, accO1, res);
    res = fmaf(inv2, accO2, res);
    res = fmaf(inv3, accO3, res);

    // e-part: sum_h inv_h * sum_i We[i, h*32+lane] * T[h,i]
#pragma unroll
    for (int h = 0; h < 4; h++) {
        float acc = 0.0f;
#pragma unroll
        for (int i = 0; i < 16; i++) {
            float t = (h < 2) ? __shfl_sync(0xffffffffu, accT0, h * 16 + i)
                              : __shfl_sync(0xffffffffu, accT1, (h - 2) * 16 + i);
            acc = fmaf(sWe[i * 128 + h * 32 + lane], t, acc);
        }
        float inv = (h == 0) ? inv0 : (h == 1) ? inv1 : (h == 2) ? inv2 : inv3;
        res = fmaf(inv, acc, res);
    }

    float* outbuf = layer ? g_h2 : g_h1;
    outbuf[n * 32 + lane] += 0.25f * res;   // skip already there; no atomics
}

// ===========================================================================
// MLP node precompute: u_src = relu(h2)@Wm1[0:32], u_dst = relu(h2)@Wm1[48:80]
// ===========================================================================
__global__ void mlp_pre_kernel(const float* __restrict__ Wm1, int N)
{
    __shared__ float sWa[1024];
    __shared__ float sWc[1024];
    for (int t = threadIdx.x; t < 1024; t += blockDim.x) {
        sWa[t] = Wm1[t];
        sWc[t] = Wm1[1536 + t];
    }
    __syncthreads();

    int n = (int)((blockIdx.x * blockDim.x + threadIdx.x) >> 5);
    int lane = threadIdx.x & 31;
    if (n >= N) return;

    float r = fmaxf(g_h2[n * 32 + lane], 0.0f);
    float us = 0.0f, ud = 0.0f;
#pragma unroll
    for (int i = 0; i < 32; i++) {
        float xi = __shfl_sync(0xffffffffu, r, i);
        us = fmaf(xi, sWa[i * 32 + lane], us);
        ud = fmaf(xi, sWc[i * 32 + lane], ud);
    }
    g_us[n * 32 + lane] = us;
    g_ud[n * 32 + lane] = ud;
}

// ===========================================================================
// Edge MLP: one warp per edge (original order).
// ===========================================================================
__global__ void edge_mlp_kernel(
    const int* __restrict__ ei, const float* __restrict__ ea,
    const float* __restrict__ Wm1, const float* __restrict__ bm1,
    const float* __restrict__ Wm2, const float* __restrict__ bm2,
    float* __restrict__ out, int E)
{
    __shared__ float sWe2[512];
    __shared__ float sb1[32];
    __shared__ float sW2[32];
    for (int t = threadIdx.x; t < 512; t += blockDim.x) sWe2[t] = Wm1[1024 + t];
    if (threadIdx.x < 32) {
        sb1[threadIdx.x] = bm1[threadIdx.x];
        sW2[threadIdx.x] = Wm2[threadIdx.x];
    }
    __syncthreads();

    int e = (int)((blockIdx.x * blockDim.x + threadIdx.x) >> 5);
    int lane = threadIdx.x & 31;
    if (e >= E) return;

    int src = ei[e];
    int dst = ei[E + e];

    float eav = (lane < 16) ? ea[(size_t)e * 16 + lane] : 0.0f;

    float t = g_us[src * 32 + lane] + g_ud[dst * 32 + lane] + sb1[lane];
#pragma unroll
    for (int i = 0; i < 16; i++) {
        float xi = __shfl_sync(0xffffffffu, eav, i);
        t = fmaf(xi, sWe2[i * 32 + lane], t);
    }
    float o = fmaxf(t, 0.0f) * sW2[lane];
#pragma unroll
    for (int off = 16; off > 0; off >>= 1)
        o += __shfl_xor_sync(0xffffffffu, o, off);
    if (lane == 0) out[e] = o + bm2[0];
}

// ===========================================================================
extern "C" void kernel_launch(void* const* d_in, const int* in_sizes, int n_in,
                              void* d_out, int out_size)
{
    const float* x  = (const float*)d_in[0];
    const float* ea = (const float*)d_in[1];
    const int*   ei = (const int*)d_in[2];

    const float* Wq1 = (const float*)d_in[3];
    const float* bq1 = (const float*)d_in[4];
    const float* Wk1 = (const float*)d_in[5];
    const float* bk1 = (const float*)d_in[6];
    const float* Wv1 = (const float*)d_in[7];
    const float* bv1 = (const float*)d_in[8];
    const float* We1 = (const float*)d_in[9];
    const float* Ws1 = (const float*)d_in[10];
    const float* bs1 = (const float*)d_in[11];

    const float* Wq2 = (const float*)d_in[12];
    const float* bq2 = (const float*)d_in[13];
    const float* Wk2 = (const float*)d_in[14];
    const float* bk2 = (const float*)d_in[15];
    const float* Wv2 = (const float*)d_in[16];
    const float* bv2 = (const float*)d_in[17];
    const float* We2 = (const float*)d_in[18];
    const float* Ws2 = (const float*)d_in[19];
    const float* bs2 = (const float*)d_in[20];

    const float* Wm1 = (const float*)d_in[21];
    const float* bm1 = (const float*)d_in[22];
    const float* Wm2 = (const float*)d_in[23];
    const float* bm2 = (const float*)d_in[24];

    float* out = (float*)d_out;

    int N = in_sizes[0] / 32;
    int E = in_sizes[1] / 16;

    int eBlocks256     = (E + 255) / 256;
    int edgeWarpBlocks = (E + 7) / 8;
    int nodeWarpBlocks = (N + 7) / 8;
    int eaSortBlocks   = (E * 16 + 255) / 256;

    // Launch order arranged so the 6th launch (ncu -s 5 -c 1) is node_attn L1.
    // 1: node_linear L1 (also zeroes g_deg)
    node_linear_kernel<<<N, 128>>>(x, 0, Wq1, bq1, Wk1, bk1, Wv1, bv1, Ws1, bs1, We1, N);
    // 2-5: CSR build + ea permute
    csr_hist_kernel<<<eBlocks256, 256>>>(ei, E);
    csr_scan_kernel<<<1, 1024>>>(N);
    csr_scatter_kernel<<<eBlocks256, 256>>>(ei, E);
    ea_sort_kernel<<<eaSortBlocks, 256>>>(ea, E);
    // 6: attention layer 1  <-- profiled launch
    node_attn_kernel<<<nodeWarpBlocks, 256>>>(We1, 0, N);

    // ---- Layer 2 ----
    node_linear_kernel<<<N, 128>>>(nullptr, 1, Wq2, bq2, Wk2, bk2, Wv2, bv2, Ws2, bs2, We2, N);
    node_attn_kernel<<<nodeWarpBlocks, 256>>>(We2, 1, N);

    // ---- Edge MLP ----
    mlp_pre_kernel<<<nodeWarpBlocks, 256>>>(Wm1, N);
    edge_mlp_kernel<<<edgeWarpBlocks, 256>>>(ei, ea, Wm1, bm1, Wm2, bm2, out, E);
}